// round 8
// baseline (speedup 1.0000x reference)
#include <cuda_runtime.h>
#include <cuda_bf16.h>
#include <cstdint>

// ---------------------------------------------------------------------------
// MentionPrunerSpanBert: B=4, T=512, L=15, D=2048, H=1024, K=205
// R7: GEMM1 consumes span_vecs fp32 DIRECTLY (cp.async fp32 tile, in-register
//     hi/lo bf16 split at fragment load) -> the 502MB split_kernel round-trip
//     is deleted. Bitwise-identical math to R6 elsewhere.
// ---------------------------------------------------------------------------

#define BB   4
#define TT   512
#define LL   15
#define DD   2048
#define HH   1024
#define KK   205
#define TL   (TT * LL)          // 7680
#define MM   (BB * TL)          // 30720
#define NPART 8
#define NSEG 8
#define SEGLEN (TL / NSEG)      // 960

#define O_PSCORE 0
#define O_TOPIDX (O_PSCORE + MM)
#define O_FVECS  (O_TOPIDX + BB * KK)
#define O_FSCORE (O_FVECS  + (size_t)BB * KK * DD)
#define O_FBEGIN (O_FSCORE + BB * KK)
#define O_FEND   (O_FBEGIN + BB * KK)
#define O_SPLEN  (O_FEND   + BB * KK)
#define O_SQMASK (O_SPLEN  + BB)
#define O_TRMASK (O_SQMASK + BB * KK * KK)

// ---------------- device scratch (no allocations allowed) -------------------
__device__ __nv_bfloat16 g_h1hi[(size_t)MM * HH];
__device__ __nv_bfloat16 g_h1lo[(size_t)MM * HH];
__device__ __nv_bfloat16 g_w1thi[(size_t)HH * DD];
__device__ __nv_bfloat16 g_w1tlo[(size_t)HH * DD];
__device__ __nv_bfloat16 g_w2thi[(size_t)HH * HH];
__device__ __nv_bfloat16 g_w2tlo[(size_t)HH * HH];
__device__ float g_spart[(size_t)MM * NPART];
__device__ unsigned long long g_cand[BB * NSEG * KK];
__device__ int   g_topidx[BB * KK];
__device__ int   g_spanlen[BB];

// ---------------- PTX helpers (all arch-agnostic, sm_80+) -------------------
__device__ __forceinline__ uint32_t smem_u32_of(const void* p) {
    uint32_t a;
    asm("{ .reg .u64 t; cvta.to.shared.u64 t, %1; cvt.u32.u64 %0, t; }" : "=r"(a) : "l"(p));
    return a;
}
#define CP16(dst, src) \
    asm volatile("cp.async.cg.shared.global [%0], [%1], 16;" :: "r"((uint32_t)(dst)), "l"(src))
#define CP_COMMIT() asm volatile("cp.async.commit_group;" ::: "memory")
#define CP_WAIT(n)  asm volatile("cp.async.wait_group %0;" :: "n"(n) : "memory")

#define LDSM_X4(R0, R1, R2, R3, addr) \
    asm volatile("ldmatrix.sync.aligned.m8n8.x4.shared.b16 {%0,%1,%2,%3}, [%4];" \
        : "=r"(R0), "=r"(R1), "=r"(R2), "=r"(R3) : "r"(addr))

#define MMA_BF16(D, A, B0, B1) \
    asm volatile("mma.sync.aligned.m16n8k16.row.col.f32.bf16.bf16.f32 " \
        "{%0,%1,%2,%3}, {%4,%5,%6,%7}, {%8,%9}, {%0,%1,%2,%3};" \
        : "+f"((D)[0]), "+f"((D)[1]), "+f"((D)[2]), "+f"((D)[3]) \
        : "r"((A)[0]), "r"((A)[1]), "r"((A)[2]), "r"((A)[3]), "r"(B0), "r"(B1))

// bf16 smem swizzle: 64B rows, 4x16B chunks
__device__ __forceinline__ uint32_t swz(int row, int chunk) {
    return (uint32_t)(row * 64 + (((chunk) ^ ((row >> 1) & 3)) & 3) * 16);
}
// fp32 smem swizzle: 128B rows, 8x16B chunks
__device__ __forceinline__ uint32_t swzf(int row, int chunk) {
    return (uint32_t)(row * 128 + (((chunk) ^ (row & 7)) & 7) * 16);
}

__device__ __forceinline__ unsigned long long score_key(float s, int idx) {
    unsigned u = __float_as_uint(s);
    u = (u & 0x80000000u) ? ~u : (u | 0x80000000u);
    return ((unsigned long long)(~u) << 32) | (unsigned)idx;
}

// split float2 -> packed bf16x2 hi + lo (RN both; identical to old split kernel)
__device__ __forceinline__ void split2(float x, float y, uint32_t& hi, uint32_t& lo) {
    __nv_bfloat16 h0 = __float2bfloat16(x);
    __nv_bfloat16 h1 = __float2bfloat16(y);
    __nv_bfloat16 l0 = __float2bfloat16(x - __bfloat162float(h0));
    __nv_bfloat16 l1 = __float2bfloat16(y - __bfloat162float(h1));
    __nv_bfloat162 hh; hh.x = h0; hh.y = h1;
    __nv_bfloat162 ll; ll.x = l0; ll.y = l1;
    hi = *reinterpret_cast<uint32_t*>(&hh);
    lo = *reinterpret_cast<uint32_t*>(&ll);
}

// ---------------------------------------------------------------------------
// transpose-split preprocessing (weights only; x-split is fused into GEMM1)
// ---------------------------------------------------------------------------
__global__ void transpose_split(const float* __restrict__ W,
                                __nv_bfloat16* __restrict__ Thi,
                                __nv_bfloat16* __restrict__ Tlo, int Kd, int N)
{
    size_t tid = (size_t)blockIdx.x * blockDim.x + threadIdx.x;
    if (tid >= (size_t)Kd * N) return;
    int k = (int)(tid % Kd);
    int n = (int)(tid / Kd);
    float v = W[(size_t)k * N + n];
    __nv_bfloat16 h = __float2bfloat16(v);
    Thi[tid] = h;
    Tlo[tid] = __float2bfloat16(v - __bfloat162float(h));
}

// ---------------------------------------------------------------------------
// GEMM1 (fused split): C = relu(A_f32 @ (Bhi+Blo)^T + bias) -> Chi/Clo bf16
// A fp32 tile cp.async'd raw; hi/lo fragments built in-register via LDS.
// Tile 128x128, BK=32, 256 thr, 3-stage, one sync/chunk, 2 CTAs/SM.
// ---------------------------------------------------------------------------
#define GBM 128
#define GBN 128
#define GBK 32
// stage layout (32KB): BH[0,8K) BL[8K,16K) AF32[16K,32K)
#define SM_BH 0
#define SM_BL 8192
#define SM_AF 16384
#define STAGE_SZ 32768
#define NSTAGE 3
#define GEMM_SMEM (NSTAGE * STAGE_SZ)

__global__ __launch_bounds__(256, 2)
void gemm1_fused(const float* __restrict__ Af,
                 const __nv_bfloat16* __restrict__ Bhi, const __nv_bfloat16* __restrict__ Blo,
                 const float* __restrict__ bias,
                 __nv_bfloat16* __restrict__ Chi, __nv_bfloat16* __restrict__ Clo,
                 int M, int N, int Kd)
{
    extern __shared__ char smem[];
    const uint32_t sb = smem_u32_of(smem);
    const int t = threadIdx.x;
    const int lane = t & 31;
    const int wid = t >> 5;
    const int wm = wid & 3;
    const int wn = wid >> 2;
    const int mBase = blockIdx.y * GBM;
    const int nBase = blockIdx.x * GBN;
    const int NC = Kd / GBK;

    float acc[2][8][4];
#pragma unroll
    for (int mi = 0; mi < 2; mi++)
#pragma unroll
        for (int ni = 0; ni < 8; ni++)
#pragma unroll
            for (int j = 0; j < 4; j++) acc[mi][ni][j] = 0.0f;

    auto load_stage = [&](int cidx, int buf) {
        const size_t ko = (size_t)cidx * GBK;
        const uint32_t stg = sb + buf * STAGE_SZ;
        // B: 512 16B chunks per matrix, 2 per thread each
#pragma unroll
        for (int p = 0; p < 2; p++) {
            const int idx = t + p * 256;
            const int row = idx >> 2;
            const int c16 = idx & 3;
            const uint32_t doff = swz(row, c16);
            const size_t boff = (size_t)(nBase + row) * Kd + ko + c16 * 8;
            CP16(stg + SM_BH + doff, Bhi + boff);
            CP16(stg + SM_BL + doff, Blo + boff);
        }
        // A fp32: 1024 16B chunks (4 floats), 4 per thread
#pragma unroll
        for (int p = 0; p < 4; p++) {
            const int idx = t + p * 256;
            const int row = idx >> 3;
            const int c8 = idx & 7;
            CP16(stg + SM_AF + swzf(row, c8),
                 Af + (size_t)(mBase + row) * Kd + ko + c8 * 4);
        }
        CP_COMMIT();
    };

    const int br = lane & 7, bblk = lane >> 3;
    const int r0 = lane >> 2;
    const int cq = (lane & 3) << 1;

    // LDS float2 from swizzled fp32 A region
    auto ldsA = [&](uint32_t stg, int row, int col) -> float2 {
        uint32_t addr = stg + SM_AF + swzf(row, col >> 2) + (col & 3) * 4;
        float2 v;
        asm volatile("ld.shared.v2.f32 {%0,%1}, [%2];" : "=f"(v.x), "=f"(v.y) : "r"(addr));
        return v;
    };

    auto compute_half = [&](uint32_t stg, int kk2) {
        uint32_t ah[2][4], al[2][4];
#pragma unroll
        for (int mi = 0; mi < 2; mi++) {
            const int rb = wm * 32 + mi * 16 + r0;
            const int cb = cq + kk2 * 16;
            float2 v0 = ldsA(stg, rb,     cb);
            float2 v1 = ldsA(stg, rb + 8, cb);
            float2 v2 = ldsA(stg, rb,     cb + 8);
            float2 v3 = ldsA(stg, rb + 8, cb + 8);
            split2(v0.x, v0.y, ah[mi][0], al[mi][0]);
            split2(v1.x, v1.y, ah[mi][1], al[mi][1]);
            split2(v2.x, v2.y, ah[mi][2], al[mi][2]);
            split2(v3.x, v3.y, ah[mi][3], al[mi][3]);
        }
        uint32_t bf[8][2];
#pragma unroll
        for (int nj = 0; nj < 4; nj++) {
            const int rowB = wn * 64 + nj * 16 + (bblk >> 1) * 8 + br;
            const uint32_t rb = swz(rowB, kk2 * 2 + (bblk & 1));
            LDSM_X4(bf[2*nj][0], bf[2*nj][1], bf[2*nj+1][0], bf[2*nj+1][1], stg + SM_BH + rb);
        }
#pragma unroll
        for (int mi = 0; mi < 2; mi++)
#pragma unroll
            for (int ni = 0; ni < 8; ni++) {
                MMA_BF16(acc[mi][ni], ah[mi], bf[ni][0], bf[ni][1]);
                MMA_BF16(acc[mi][ni], al[mi], bf[ni][0], bf[ni][1]);
            }
#pragma unroll
        for (int nj = 0; nj < 4; nj++) {
            const int rowB = wn * 64 + nj * 16 + (bblk >> 1) * 8 + br;
            const uint32_t rb = swz(rowB, kk2 * 2 + (bblk & 1));
            LDSM_X4(bf[2*nj][0], bf[2*nj][1], bf[2*nj+1][0], bf[2*nj+1][1], stg + SM_BL + rb);
        }
#pragma unroll
        for (int mi = 0; mi < 2; mi++)
#pragma unroll
            for (int ni = 0; ni < 8; ni++)
                MMA_BF16(acc[mi][ni], ah[mi], bf[ni][0], bf[ni][1]);
    };

    load_stage(0, 0);
    load_stage(1, 1);

#pragma unroll 1
    for (int c = 0; c < NC; c++) {
        const int buf = c % NSTAGE;
        if (c < NC - 1) CP_WAIT(1); else CP_WAIT(0);
        __syncthreads();
        const uint32_t stg = sb + buf * STAGE_SZ;
        compute_half(stg, 0);
        if (c + 2 < NC) load_stage(c + 2, (c + 2) % NSTAGE);
        compute_half(stg, 1);
    }

    // epilogue: bias + relu + hi/lo re-split
    const int c0 = (lane & 3) << 1;
#pragma unroll
    for (int mi = 0; mi < 2; mi++) {
        const int rowA = mBase + wm * 32 + mi * 16 + r0;
#pragma unroll
        for (int ni = 0; ni < 8; ni++) {
            const int col = nBase + wn * 64 + ni * 8 + c0;
            const float bv0 = bias[col], bv1 = bias[col + 1];
            float v0 = acc[mi][ni][0] + bv0;  v0 = v0 > 0.0f ? v0 : 0.0f;
            float v1 = acc[mi][ni][1] + bv1;  v1 = v1 > 0.0f ? v1 : 0.0f;
            float v2 = acc[mi][ni][2] + bv0;  v2 = v2 > 0.0f ? v2 : 0.0f;
            float v3 = acc[mi][ni][3] + bv1;  v3 = v3 > 0.0f ? v3 : 0.0f;
            uint32_t hh, ll;
            split2(v0, v1, hh, ll);
            *reinterpret_cast<uint32_t*>(Chi + (size_t)rowA * N + col) = hh;
            *reinterpret_cast<uint32_t*>(Clo + (size_t)rowA * N + col) = ll;
            split2(v2, v3, hh, ll);
            *reinterpret_cast<uint32_t*>(Chi + (size_t)(rowA + 8) * N + col) = hh;
            *reinterpret_cast<uint32_t*>(Clo + (size_t)(rowA + 8) * N + col) = ll;
        }
    }
}

// ---------------------------------------------------------------------------
// GEMM2 (split-bf16 A from gmem) + fused W3 GEMV -> score partials.
// Stage layout: AH[0,8K) AL[8K,16K) BH[16K,24K) BL[24K,32K)
// ---------------------------------------------------------------------------
#define SM2_AH 0
#define SM2_AL 8192
#define SM2_BH 16384
#define SM2_BL 24576

__global__ __launch_bounds__(256, 2)
void gemm2_mma(const __nv_bfloat16* __restrict__ Ahi, const __nv_bfloat16* __restrict__ Alo,
               const __nv_bfloat16* __restrict__ Bhi, const __nv_bfloat16* __restrict__ Blo,
               const float* __restrict__ bias,
               const float* __restrict__ W3,
               float* __restrict__ spart,
               int M, int N, int Kd)
{
    extern __shared__ char smem[];
    const uint32_t sb = smem_u32_of(smem);
    const int t = threadIdx.x;
    const int lane = t & 31;
    const int wid = t >> 5;
    const int wm = wid & 3;
    const int wn = wid >> 2;
    const int mBase = blockIdx.y * GBM;
    const int nBase = blockIdx.x * GBN;
    const int NC = Kd / GBK;

    float acc[2][8][4];
#pragma unroll
    for (int mi = 0; mi < 2; mi++)
#pragma unroll
        for (int ni = 0; ni < 8; ni++)
#pragma unroll
            for (int j = 0; j < 4; j++) acc[mi][ni][j] = 0.0f;

    auto load_stage = [&](int cidx, int buf) {
        const size_t ko = (size_t)cidx * GBK;
        const uint32_t stg = sb + buf * STAGE_SZ;
#pragma unroll
        for (int p = 0; p < 2; p++) {
            const int idx = t + p * 256;
            const int row = idx >> 2;
            const int c16 = idx & 3;
            const uint32_t doff = swz(row, c16);
            const size_t aoff = (size_t)(mBase + row) * Kd + ko + c16 * 8;
            const size_t boff = (size_t)(nBase + row) * Kd + ko + c16 * 8;
            CP16(stg + SM2_AH + doff, Ahi + aoff);
            CP16(stg + SM2_AL + doff, Alo + aoff);
            CP16(stg + SM2_BH + doff, Bhi + boff);
            CP16(stg + SM2_BL + doff, Blo + boff);
        }
        CP_COMMIT();
    };

    const int ar = lane & 15, ac = lane >> 4;
    const int br = lane & 7,  bblk = lane >> 3;

    auto compute_half = [&](uint32_t stg, int kk2) {
        uint32_t ah[2][4], al[2][4];
#pragma unroll
        for (int mi = 0; mi < 2; mi++) {
            const int rowA = wm * 32 + mi * 16 + ar;
            const uint32_t ra = swz(rowA, kk2 * 2 + ac);
            LDSM_X4(ah[mi][0], ah[mi][1], ah[mi][2], ah[mi][3], stg + SM2_AH + ra);
            LDSM_X4(al[mi][0], al[mi][1], al[mi][2], al[mi][3], stg + SM2_AL + ra);
        }
        uint32_t bf[8][2];
#pragma unroll
        for (int nj = 0; nj < 4; nj++) {
            const int rowB = wn * 64 + nj * 16 + (bblk >> 1) * 8 + br;
            const uint32_t rb = swz(rowB, kk2 * 2 + (bblk & 1));
            LDSM_X4(bf[2*nj][0], bf[2*nj][1], bf[2*nj+1][0], bf[2*nj+1][1], stg + SM2_BH + rb);
        }
#pragma unroll
        for (int mi = 0; mi < 2; mi++)
#pragma unroll
            for (int ni = 0; ni < 8; ni++) {
                MMA_BF16(acc[mi][ni], ah[mi], bf[ni][0], bf[ni][1]);
                MMA_BF16(acc[mi][ni], al[mi], bf[ni][0], bf[ni][1]);
            }
#pragma unroll
        for (int nj = 0; nj < 4; nj++) {
            const int rowB = wn * 64 + nj * 16 + (bblk >> 1) * 8 + br;
            const uint32_t rb = swz(rowB, kk2 * 2 + (bblk & 1));
            LDSM_X4(bf[2*nj][0], bf[2*nj][1], bf[2*nj+1][0], bf[2*nj+1][1], stg + SM2_BL + rb);
        }
#pragma unroll
        for (int mi = 0; mi < 2; mi++)
#pragma unroll
            for (int ni = 0; ni < 8; ni++)
                MMA_BF16(acc[mi][ni], ah[mi], bf[ni][0], bf[ni][1]);
    };

    load_stage(0, 0);
    load_stage(1, 1);

#pragma unroll 1
    for (int c = 0; c < NC; c++) {
        const int buf = c % NSTAGE;
        if (c < NC - 1) CP_WAIT(1); else CP_WAIT(0);
        __syncthreads();
        const uint32_t stg = sb + buf * STAGE_SZ;
        compute_half(stg, 0);
        if (c + 2 < NC) load_stage(c + 2, (c + 2) % NSTAGE);
        compute_half(stg, 1);
    }

    // fused W3 GEMV epilogue
    const int r0 = lane >> 2;
    const int c0 = (lane & 3) << 1;
    float ps[2][2] = {{0.0f, 0.0f}, {0.0f, 0.0f}};
#pragma unroll
    for (int mi = 0; mi < 2; mi++) {
#pragma unroll
        for (int ni = 0; ni < 8; ni++) {
            const int col = nBase + wn * 64 + ni * 8 + c0;
            const float bv0 = bias[col], bv1 = bias[col + 1];
            const float w0 = W3[col], w1 = W3[col + 1];
            float v0 = acc[mi][ni][0] + bv0;  v0 = v0 > 0.0f ? v0 : 0.0f;
            float v1 = acc[mi][ni][1] + bv1;  v1 = v1 > 0.0f ? v1 : 0.0f;
            float v2 = acc[mi][ni][2] + bv0;  v2 = v2 > 0.0f ? v2 : 0.0f;
            float v3 = acc[mi][ni][3] + bv1;  v3 = v3 > 0.0f ? v3 : 0.0f;
            ps[mi][0] = fmaf(v0, w0, fmaf(v1, w1, ps[mi][0]));
            ps[mi][1] = fmaf(v2, w0, fmaf(v3, w1, ps[mi][1]));
        }
#pragma unroll
        for (int o = 1; o <= 2; o <<= 1) {
            ps[mi][0] += __shfl_xor_sync(0xffffffffu, ps[mi][0], o);
            ps[mi][1] += __shfl_xor_sync(0xffffffffu, ps[mi][1], o);
        }
    }
    float* pssum = reinterpret_cast<float*>(smem);
    __syncthreads();
    if ((lane & 3) == 0) {
#pragma unroll
        for (int mi = 0; mi < 2; mi++) {
            int lr = wm * 32 + mi * 16 + r0;
            pssum[(lr)     * 2 + wn] = ps[mi][0];
            pssum[(lr + 8) * 2 + wn] = ps[mi][1];
        }
    }
    __syncthreads();
    if (t < 128) {
        float s = pssum[t * 2] + pssum[t * 2 + 1];
        spart[(size_t)(mBase + t) * NPART + blockIdx.x] = s;
    }
}

// ---------------------------------------------------------------------------
__global__ void score_finish(const float* __restrict__ spart,
                             const float* __restrict__ b3,
                             const float* __restrict__ mask,
                             float* __restrict__ out)
{
    int row = blockIdx.x * blockDim.x + threadIdx.x;
    if (row >= MM) return;
    const float* p = spart + (size_t)row * NPART;
    float s = b3[0];
#pragma unroll
    for (int j = 0; j < NPART; j++) s += p[j];
    out[O_PSCORE + row] = s - (1.0f - mask[row]) * 10000.0f;
}

// ---------------------------------------------------------------------------
__global__ void topk_phaseA(const float* __restrict__ out_ro,
                            unsigned long long* __restrict__ cand)
{
    __shared__ unsigned long long key[1024];
    const int b = blockIdx.x >> 3;
    const int seg = blockIdx.x & 7;
    const int t = threadIdx.x;          // 512
    const int base = seg * SEGLEN;

    for (int i = t; i < 1024; i += 512) {
        unsigned long long kv = 0xFFFFFFFFFFFFFFFFull;
        if (i < SEGLEN) {
            int gi = base + i;
            kv = score_key(out_ro[O_PSCORE + b * TL + gi], gi);
        }
        key[i] = kv;
    }
    __syncthreads();

    for (int k = 2; k <= 1024; k <<= 1)
        for (int j = k >> 1; j > 0; j >>= 1) {
            for (int i = t; i < 1024; i += 512) {
                int ixj = i ^ j;
                if (ixj > i) {
                    unsigned long long a = key[i], c = key[ixj];
                    bool up = ((i & k) == 0);
                    if ((a > c) == up) { key[i] = c; key[ixj] = a; }
                }
            }
            __syncthreads();
        }

    if (t < KK) cand[(b * NSEG + seg) * KK + t] = key[t];
}

__global__ void topk_phaseB(const unsigned long long* __restrict__ cand,
                            const int* __restrict__ seqlen,
                            float* __restrict__ out,
                            int* __restrict__ topidx,
                            int* __restrict__ splen)
{
    __shared__ unsigned long long key[2048];
    const int b = blockIdx.x;
    const int t = threadIdx.x;          // 1024

    for (int i = t; i < 2048; i += 1024)
        key[i] = (i < NSEG * KK) ? cand[b * NSEG * KK + i] : 0xFFFFFFFFFFFFFFFFull;
    __syncthreads();

    for (int k = 2; k <= 2048; k <<= 1)
        for (int j = k >> 1; j > 0; j >>= 1) {
            for (int i = t; i < 2048; i += 1024) {
                int ixj = i ^ j;
                if (ixj > i) {
                    unsigned long long a = key[i], c = key[ixj];
                    bool up = ((i & k) == 0);
                    if ((a > c) == up) { key[i] = c; key[ixj] = a; }
                }
            }
            __syncthreads();
        }

    __shared__ int sidx[256];
    if (t < 256) sidx[t] = (t < KK) ? (int)(key[t] & 0xFFFFFFFFull) : 0x7FFFFFFF;
    __syncthreads();
    for (int k = 2; k <= 256; k <<= 1)
        for (int j = k >> 1; j > 0; j >>= 1) {
            if (t < 256) {
                int i = t, ixj = i ^ j;
                if (ixj > i) {
                    int a = sidx[i], c = sidx[ixj];
                    bool up = ((i & k) == 0);
                    if ((a > c) == up) { sidx[i] = c; sidx[ixj] = a; }
                }
            }
            __syncthreads();
        }

    if (t < KK) {
        topidx[b * KK + t] = sidx[t];
        out[O_TOPIDX + b * KK + t] = (float)sidx[t];
    }
    if (t == 0) {
        int len = (int)ceilf((float)seqlen[b] * 0.4f);
        splen[b] = len;
        out[O_SPLEN + b] = (float)len;
    }
}

__global__ void gather_kernel(const float* __restrict__ span_vecs,
                              const int* __restrict__ span_begin,
                              const int* __restrict__ span_end,
                              const int* __restrict__ topidx,
                              float* __restrict__ out)
{
    int blk = blockIdx.x;
    int b = blk / KK, k = blk % KK;
    int idx = topidx[b * KK + k];
    const float* src = span_vecs + ((size_t)b * TL + idx) * DD;
    float* dst = out + O_FVECS + ((size_t)b * KK + k) * DD;
    for (int i = threadIdx.x; i < DD; i += 256) dst[i] = src[i];
    if (threadIdx.x == 0) {
        int g = b * TL + idx;
        out[O_FSCORE + b * KK + k] = out[O_PSCORE + g];
        out[O_FBEGIN + b * KK + k] = (float)span_begin[g];
        out[O_FEND   + b * KK + k] = (float)span_end[g];
    }
}

__global__ void mask_kernel(const int* __restrict__ splen, float* __restrict__ out)
{
    int i = blockIdx.x * blockDim.x + threadIdx.x;
    const int per = KK * KK;
    if (i >= BB * per) return;
    int b = i / per, r = i % per;
    int ii = r / KK, jj = r % KK;
    int len = splen[b];
    float v = (ii < len && jj < len) ? 1.0f : 0.0f;
    out[O_SQMASK + i] = v;
    out[O_TRMASK + i] = (jj <= ii) ? v : 0.0f;
}

// ---------------------------------------------------------------------------
extern "C" void kernel_launch(void* const* d_in, const int* in_sizes, int n_in,
                              void* d_out, int out_size)
{
    const float* span_vecs  = (const float*)d_in[0];
    const float* span_mask  = (const float*)d_in[1];
    const int*   span_begin = (const int*)  d_in[2];
    const int*   span_end   = (const int*)  d_in[3];
    const int*   seqlen     = (const int*)  d_in[4];
    const float* W1 = (const float*)d_in[5];
    const float* b1 = (const float*)d_in[6];
    const float* W2 = (const float*)d_in[7];
    const float* b2 = (const float*)d_in[8];
    const float* W3 = (const float*)d_in[9];
    const float* b3 = (const float*)d_in[10];
    float* out = (float*)d_out;

    __nv_bfloat16 *h1hi, *h1lo, *w1thi, *w1tlo, *w2thi, *w2tlo;
    float* spart; unsigned long long* cand; int *topidx, *splen;
    cudaGetSymbolAddress((void**)&h1hi,  g_h1hi);
    cudaGetSymbolAddress((void**)&h1lo,  g_h1lo);
    cudaGetSymbolAddress((void**)&w1thi, g_w1thi);
    cudaGetSymbolAddress((void**)&w1tlo, g_w1tlo);
    cudaGetSymbolAddress((void**)&w2thi, g_w2thi);
    cudaGetSymbolAddress((void**)&w2tlo, g_w2tlo);
    cudaGetSymbolAddress((void**)&spart, g_spart);
    cudaGetSymbolAddress((void**)&cand,  g_cand);
    cudaGetSymbolAddress((void**)&topidx, g_topidx);
    cudaGetSymbolAddress((void**)&splen,  g_spanlen);

    cudaFuncSetAttribute(gemm1_fused, cudaFuncAttributeMaxDynamicSharedMemorySize, GEMM_SMEM);
    cudaFuncSetAttribute(gemm2_mma,   cudaFuncAttributeMaxDynamicSharedMemorySize, GEMM_SMEM);

    // 1) weight transpose-splits (x split is fused into GEMM1)
    {
        size_t n = (size_t)DD * HH;
        transpose_split<<<(unsigned)((n + 255) / 256), 256>>>(W1, w1thi, w1tlo, DD, HH);
    }
    {
        size_t n = (size_t)HH * HH;
        transpose_split<<<(unsigned)((n + 255) / 256), 256>>>(W2, w2thi, w2tlo, HH, HH);
    }

    // 2) GEMM1: relu(x @ W1 + b1) -> h1 (split bf16), x read as fp32
    {
        dim3 grid(HH / GBN, MM / GBM);   // (8, 240)
        gemm1_fused<<<grid, 256, GEMM_SMEM>>>(span_vecs, w1thi, w1tlo, b1,
                                              h1hi, h1lo, MM, HH, DD);
    }
    // 3) GEMM2 + fused W3 GEMV -> score partials
    {
        dim3 grid(HH / GBN, MM / GBM);
        gemm2_mma<<<grid, 256, GEMM_SMEM>>>(h1hi, h1lo, w2thi, w2tlo, b2,
                                            W3, spart, MM, HH, HH);
    }

    // 4) finish scores + penalty
    score_finish<<<(MM + 255) / 256, 256>>>(spart, b3, span_mask, out);

    // 5) top-K per batch: two-phase
    topk_phaseA<<<BB * NSEG, 512>>>(out, cand);
    topk_phaseB<<<BB, 1024>>>(cand, seqlen, out, topidx, splen);

    // 6) gathers
    gather_kernel<<<BB * KK, 256>>>(span_vecs, span_begin, span_end, topidx, out);

    // 7) masks
    {
        int n = BB * KK * KK;
        mask_kernel<<<(n + 255) / 256, 256>>>(splen, out);
    }
}

// round 9
// speedup vs baseline: 1.0820x; 1.0820x over previous
#include <cuda_runtime.h>
#include <cuda_bf16.h>
#include <cstdint>

// ---------------------------------------------------------------------------
// MentionPrunerSpanBert: B=4, T=512, L=15, D=2048, H=1024, K=205
// R8: revert to R6's proven GEMM structure (R7's fused A-split was
//     issue-bound poison: +180us). Fuse score_finish into topk_phaseA,
//     widen split_kernel stores, vectorize gather.
// ---------------------------------------------------------------------------

#define BB   4
#define TT   512
#define LL   15
#define DD   2048
#define HH   1024
#define KK   205
#define TL   (TT * LL)          // 7680
#define MM   (BB * TL)          // 30720
#define NPART 8
#define NSEG 8
#define SEGLEN (TL / NSEG)      // 960

#define O_PSCORE 0
#define O_TOPIDX (O_PSCORE + MM)
#define O_FVECS  (O_TOPIDX + BB * KK)
#define O_FSCORE (O_FVECS  + (size_t)BB * KK * DD)
#define O_FBEGIN (O_FSCORE + BB * KK)
#define O_FEND   (O_FBEGIN + BB * KK)
#define O_SPLEN  (O_FEND   + BB * KK)
#define O_SQMASK (O_SPLEN  + BB)
#define O_TRMASK (O_SQMASK + BB * KK * KK)

// ---------------- device scratch (no allocations allowed) -------------------
__device__ __nv_bfloat16 g_xhi[(size_t)MM * DD];
__device__ __nv_bfloat16 g_xlo[(size_t)MM * DD];
__device__ __nv_bfloat16 g_h1hi[(size_t)MM * HH];
__device__ __nv_bfloat16 g_h1lo[(size_t)MM * HH];
__device__ __nv_bfloat16 g_w1thi[(size_t)HH * DD];
__device__ __nv_bfloat16 g_w1tlo[(size_t)HH * DD];
__device__ __nv_bfloat16 g_w2thi[(size_t)HH * HH];
__device__ __nv_bfloat16 g_w2tlo[(size_t)HH * HH];
__device__ float g_spart[(size_t)MM * NPART];
__device__ unsigned long long g_cand[BB * NSEG * KK];
__device__ int   g_topidx[BB * KK];
__device__ int   g_spanlen[BB];

// ---------------- PTX helpers (all arch-agnostic, sm_80+) -------------------
__device__ __forceinline__ uint32_t smem_u32_of(const void* p) {
    uint32_t a;
    asm("{ .reg .u64 t; cvta.to.shared.u64 t, %1; cvt.u32.u64 %0, t; }" : "=r"(a) : "l"(p));
    return a;
}
#define CP16(dst, src) \
    asm volatile("cp.async.cg.shared.global [%0], [%1], 16;" :: "r"((uint32_t)(dst)), "l"(src))
#define CP_COMMIT() asm volatile("cp.async.commit_group;" ::: "memory")
#define CP_WAIT(n)  asm volatile("cp.async.wait_group %0;" :: "n"(n) : "memory")

#define LDSM_X4(R0, R1, R2, R3, addr) \
    asm volatile("ldmatrix.sync.aligned.m8n8.x4.shared.b16 {%0,%1,%2,%3}, [%4];" \
        : "=r"(R0), "=r"(R1), "=r"(R2), "=r"(R3) : "r"(addr))

#define MMA_BF16(D, A, B0, B1) \
    asm volatile("mma.sync.aligned.m16n8k16.row.col.f32.bf16.bf16.f32 " \
        "{%0,%1,%2,%3}, {%4,%5,%6,%7}, {%8,%9}, {%0,%1,%2,%3};" \
        : "+f"((D)[0]), "+f"((D)[1]), "+f"((D)[2]), "+f"((D)[3]) \
        : "r"((A)[0]), "r"((A)[1]), "r"((A)[2]), "r"((A)[3]), "r"(B0), "r"(B1))

__device__ __forceinline__ uint32_t swz(int row, int chunk) {
    return (uint32_t)(row * 64 + (((chunk) ^ ((row >> 1) & 3)) & 3) * 16);
}

__device__ __forceinline__ unsigned long long score_key(float s, int idx) {
    unsigned u = __float_as_uint(s);
    u = (u & 0x80000000u) ? ~u : (u | 0x80000000u);
    return ((unsigned long long)(~u) << 32) | (unsigned)idx;
}

__device__ __forceinline__ uint32_t pack_split_hi(float x, float y, uint32_t& lo) {
    __nv_bfloat16 h0 = __float2bfloat16(x);
    __nv_bfloat16 h1 = __float2bfloat16(y);
    __nv_bfloat16 l0 = __float2bfloat16(x - __bfloat162float(h0));
    __nv_bfloat16 l1 = __float2bfloat16(y - __bfloat162float(h1));
    __nv_bfloat162 hh; hh.x = h0; hh.y = h1;
    __nv_bfloat162 ll; ll.x = l0; ll.y = l1;
    lo = *reinterpret_cast<uint32_t*>(&ll);
    return *reinterpret_cast<uint32_t*>(&hh);
}

// ---------------------------------------------------------------------------
// Split x: 8 elements per thread, 16B stores
// ---------------------------------------------------------------------------
__global__ void split_kernel(const float4* __restrict__ x,
                             uint4* __restrict__ hi,
                             uint4* __restrict__ lo, size_t n8)
{
    size_t i = (size_t)blockIdx.x * blockDim.x + threadIdx.x;
    if (i >= n8) return;
    float4 a = x[2 * i], b = x[2 * i + 1];
    uint4 h, l;
    h.x = pack_split_hi(a.x, a.y, l.x);
    h.y = pack_split_hi(a.z, a.w, l.y);
    h.z = pack_split_hi(b.x, b.y, l.z);
    h.w = pack_split_hi(b.z, b.w, l.w);
    hi[i] = h;
    lo[i] = l;
}

// W [K,N] row-major -> WT [N,K] (K-major) split into hi/lo bf16
__global__ void transpose_split(const float* __restrict__ W,
                                __nv_bfloat16* __restrict__ Thi,
                                __nv_bfloat16* __restrict__ Tlo, int Kd, int N)
{
    size_t tid = (size_t)blockIdx.x * blockDim.x + threadIdx.x;
    if (tid >= (size_t)Kd * N) return;
    int k = (int)(tid % Kd);
    int n = (int)(tid / Kd);
    float v = W[(size_t)k * N + n];
    __nv_bfloat16 h = __float2bfloat16(v);
    Thi[tid] = h;
    Tlo[tid] = __float2bfloat16(v - __bfloat162float(h));
}

// ---------------------------------------------------------------------------
// Split-bf16 HMMA GEMM (R6-proven): tile 128x128, BK=32, 256 thr,
// 3-stage cp.async, swizzled smem, one sync/chunk, mid-chunk prefetch,
// 2 CTAs/SM.  MODE 1: Chi/Clo out.  MODE 2: fused W3 GEMV partials.
// ---------------------------------------------------------------------------
#define GBM 128
#define GBN 128
#define GBK 32
#define SM_AH 0
#define SM_AL 8192
#define SM_BH 16384
#define SM_BL 24576
#define STAGE_SZ 32768
#define NSTAGE 3
#define GEMM_SMEM (NSTAGE * STAGE_SZ)

template <int MODE>
__global__ __launch_bounds__(256, 2)
void gemm3_mma(const __nv_bfloat16* __restrict__ Ahi, const __nv_bfloat16* __restrict__ Alo,
               const __nv_bfloat16* __restrict__ Bhi, const __nv_bfloat16* __restrict__ Blo,
               const float* __restrict__ bias,
               const float* __restrict__ W3,
               float* __restrict__ spart,
               __nv_bfloat16* __restrict__ Chi, __nv_bfloat16* __restrict__ Clo,
               int M, int N, int Kd)
{
    extern __shared__ char smem[];
    const uint32_t sb = smem_u32_of(smem);
    const int t = threadIdx.x;
    const int lane = t & 31;
    const int wid = t >> 5;
    const int wm = wid & 3;
    const int wn = wid >> 2;
    const int mBase = blockIdx.y * GBM;
    const int nBase = blockIdx.x * GBN;
    const int NC = Kd / GBK;

    float acc[2][8][4];
#pragma unroll
    for (int mi = 0; mi < 2; mi++)
#pragma unroll
        for (int ni = 0; ni < 8; ni++)
#pragma unroll
            for (int j = 0; j < 4; j++) acc[mi][ni][j] = 0.0f;

    auto load_stage = [&](int cidx, int buf) {
        const size_t ko = (size_t)cidx * GBK;
        const uint32_t stg = sb + buf * STAGE_SZ;
#pragma unroll
        for (int p = 0; p < 2; p++) {
            const int idx = t + p * 256;
            const int row = idx >> 2;
            const int c16 = idx & 3;
            const uint32_t doff = swz(row, c16);
            const size_t aoff = (size_t)(mBase + row) * Kd + ko + c16 * 8;
            const size_t boff = (size_t)(nBase + row) * Kd + ko + c16 * 8;
            CP16(stg + SM_AH + doff, Ahi + aoff);
            CP16(stg + SM_AL + doff, Alo + aoff);
            CP16(stg + SM_BH + doff, Bhi + boff);
            CP16(stg + SM_BL + doff, Blo + boff);
        }
        CP_COMMIT();
    };

    const int ar = lane & 15, ac = lane >> 4;
    const int br = lane & 7,  bblk = lane >> 3;

    auto compute_half = [&](uint32_t stg, int kk2) {
        uint32_t ah[2][4], al[2][4];
#pragma unroll
        for (int mi = 0; mi < 2; mi++) {
            const int rowA = wm * 32 + mi * 16 + ar;
            const uint32_t ra = swz(rowA, kk2 * 2 + ac);
            LDSM_X4(ah[mi][0], ah[mi][1], ah[mi][2], ah[mi][3], stg + SM_AH + ra);
            LDSM_X4(al[mi][0], al[mi][1], al[mi][2], al[mi][3], stg + SM_AL + ra);
        }
        uint32_t bf[8][2];
#pragma unroll
        for (int nj = 0; nj < 4; nj++) {
            const int rowB = wn * 64 + nj * 16 + (bblk >> 1) * 8 + br;
            const uint32_t rb = swz(rowB, kk2 * 2 + (bblk & 1));
            LDSM_X4(bf[2*nj][0], bf[2*nj][1], bf[2*nj+1][0], bf[2*nj+1][1], stg + SM_BH + rb);
        }
#pragma unroll
        for (int mi = 0; mi < 2; mi++)
#pragma unroll
            for (int ni = 0; ni < 8; ni++) {
                MMA_BF16(acc[mi][ni], ah[mi], bf[ni][0], bf[ni][1]);
                MMA_BF16(acc[mi][ni], al[mi], bf[ni][0], bf[ni][1]);
            }
#pragma unroll
        for (int nj = 0; nj < 4; nj++) {
            const int rowB = wn * 64 + nj * 16 + (bblk >> 1) * 8 + br;
            const uint32_t rb = swz(rowB, kk2 * 2 + (bblk & 1));
            LDSM_X4(bf[2*nj][0], bf[2*nj][1], bf[2*nj+1][0], bf[2*nj+1][1], stg + SM_BL + rb);
        }
#pragma unroll
        for (int mi = 0; mi < 2; mi++)
#pragma unroll
            for (int ni = 0; ni < 8; ni++)
                MMA_BF16(acc[mi][ni], ah[mi], bf[ni][0], bf[ni][1]);
    };

    load_stage(0, 0);
    load_stage(1, 1);

#pragma unroll 1
    for (int c = 0; c < NC; c++) {
        const int buf = c % NSTAGE;
        if (c < NC - 1) CP_WAIT(1); else CP_WAIT(0);
        __syncthreads();
        const uint32_t stg = sb + buf * STAGE_SZ;
        compute_half(stg, 0);
        if (c + 2 < NC) load_stage(c + 2, (c + 2) % NSTAGE);
        compute_half(stg, 1);
    }

    // ---- epilogue ----
    const int r0 = lane >> 2;
    const int c0 = (lane & 3) << 1;

    if (MODE == 1) {
#pragma unroll
        for (int mi = 0; mi < 2; mi++) {
            const int rowA = mBase + wm * 32 + mi * 16 + r0;
#pragma unroll
            for (int ni = 0; ni < 8; ni++) {
                const int col = nBase + wn * 64 + ni * 8 + c0;
                const float bv0 = bias[col], bv1 = bias[col + 1];
                float v0 = acc[mi][ni][0] + bv0;  v0 = v0 > 0.0f ? v0 : 0.0f;
                float v1 = acc[mi][ni][1] + bv1;  v1 = v1 > 0.0f ? v1 : 0.0f;
                float v2 = acc[mi][ni][2] + bv0;  v2 = v2 > 0.0f ? v2 : 0.0f;
                float v3 = acc[mi][ni][3] + bv1;  v3 = v3 > 0.0f ? v3 : 0.0f;
                uint32_t hh, ll;
                hh = pack_split_hi(v0, v1, ll);
                *reinterpret_cast<uint32_t*>(Chi + (size_t)rowA * N + col) = hh;
                *reinterpret_cast<uint32_t*>(Clo + (size_t)rowA * N + col) = ll;
                hh = pack_split_hi(v2, v3, ll);
                *reinterpret_cast<uint32_t*>(Chi + (size_t)(rowA + 8) * N + col) = hh;
                *reinterpret_cast<uint32_t*>(Clo + (size_t)(rowA + 8) * N + col) = ll;
            }
        }
    } else {
        float ps[2][2] = {{0.0f, 0.0f}, {0.0f, 0.0f}};
#pragma unroll
        for (int mi = 0; mi < 2; mi++) {
#pragma unroll
            for (int ni = 0; ni < 8; ni++) {
                const int col = nBase + wn * 64 + ni * 8 + c0;
                const float bv0 = bias[col], bv1 = bias[col + 1];
                const float w0 = W3[col], w1 = W3[col + 1];
                float v0 = acc[mi][ni][0] + bv0;  v0 = v0 > 0.0f ? v0 : 0.0f;
                float v1 = acc[mi][ni][1] + bv1;  v1 = v1 > 0.0f ? v1 : 0.0f;
                float v2 = acc[mi][ni][2] + bv0;  v2 = v2 > 0.0f ? v2 : 0.0f;
                float v3 = acc[mi][ni][3] + bv1;  v3 = v3 > 0.0f ? v3 : 0.0f;
                ps[mi][0] = fmaf(v0, w0, fmaf(v1, w1, ps[mi][0]));
                ps[mi][1] = fmaf(v2, w0, fmaf(v3, w1, ps[mi][1]));
            }
#pragma unroll
            for (int o = 1; o <= 2; o <<= 1) {
                ps[mi][0] += __shfl_xor_sync(0xffffffffu, ps[mi][0], o);
                ps[mi][1] += __shfl_xor_sync(0xffffffffu, ps[mi][1], o);
            }
        }
        float* pssum = reinterpret_cast<float*>(smem);
        __syncthreads();
        if ((lane & 3) == 0) {
#pragma unroll
            for (int mi = 0; mi < 2; mi++) {
                int lr = wm * 32 + mi * 16 + r0;
                pssum[(lr)     * 2 + wn] = ps[mi][0];
                pssum[(lr + 8) * 2 + wn] = ps[mi][1];
            }
        }
        __syncthreads();
        if (t < 128) {
            float s = pssum[t * 2] + pssum[t * 2 + 1];
            spart[(size_t)(mBase + t) * NPART + blockIdx.x] = s;
        }
    }
}

// ---------------------------------------------------------------------------
// Top-K phase A (fused with score finish): 32 blocks (batch x 8 segments).
// Each block finalizes the scores for its 960 rows (sum partials + b3 +
// penalty), writes prune_scores, then sorts and emits its local top-205.
// ---------------------------------------------------------------------------
__global__ void topk_phaseA(const float* __restrict__ spart,
                            const float* __restrict__ b3,
                            const float* __restrict__ mask,
                            float* __restrict__ out,
                            unsigned long long* __restrict__ cand)
{
    __shared__ unsigned long long key[1024];
    const int b = blockIdx.x >> 3;
    const int seg = blockIdx.x & 7;
    const int t = threadIdx.x;          // 512
    const int base = seg * SEGLEN;
    const float bias3 = b3[0];

    for (int i = t; i < 1024; i += 512) {
        unsigned long long kv = 0xFFFFFFFFFFFFFFFFull;
        if (i < SEGLEN) {
            int gi = base + i;
            int row = b * TL + gi;
            const float* p = spart + (size_t)row * NPART;
            float s = bias3;
#pragma unroll
            for (int j = 0; j < NPART; j++) s += p[j];
            s -= (1.0f - mask[row]) * 10000.0f;
            out[O_PSCORE + row] = s;
            kv = score_key(s, gi);
        }
        key[i] = kv;
    }
    __syncthreads();

    for (int k = 2; k <= 1024; k <<= 1)
        for (int j = k >> 1; j > 0; j >>= 1) {
            for (int i = t; i < 1024; i += 512) {
                int ixj = i ^ j;
                if (ixj > i) {
                    unsigned long long a = key[i], c = key[ixj];
                    bool up = ((i & k) == 0);
                    if ((a > c) == up) { key[i] = c; key[ixj] = a; }
                }
            }
            __syncthreads();
        }

    if (t < KK) cand[(b * NSEG + seg) * KK + t] = key[t];
}

__global__ void topk_phaseB(const unsigned long long* __restrict__ cand,
                            const int* __restrict__ seqlen,
                            float* __restrict__ out,
                            int* __restrict__ topidx,
                            int* __restrict__ splen)
{
    __shared__ unsigned long long key[2048];
    const int b = blockIdx.x;
    const int t = threadIdx.x;          // 1024

    for (int i = t; i < 2048; i += 1024)
        key[i] = (i < NSEG * KK) ? cand[b * NSEG * KK + i] : 0xFFFFFFFFFFFFFFFFull;
    __syncthreads();

    for (int k = 2; k <= 2048; k <<= 1)
        for (int j = k >> 1; j > 0; j >>= 1) {
            for (int i = t; i < 2048; i += 1024) {
                int ixj = i ^ j;
                if (ixj > i) {
                    unsigned long long a = key[i], c = key[ixj];
                    bool up = ((i & k) == 0);
                    if ((a > c) == up) { key[i] = c; key[ixj] = a; }
                }
            }
            __syncthreads();
        }

    __shared__ int sidx[256];
    if (t < 256) sidx[t] = (t < KK) ? (int)(key[t] & 0xFFFFFFFFull) : 0x7FFFFFFF;
    __syncthreads();
    for (int k = 2; k <= 256; k <<= 1)
        for (int j = k >> 1; j > 0; j >>= 1) {
            if (t < 256) {
                int i = t, ixj = i ^ j;
                if (ixj > i) {
                    int a = sidx[i], c = sidx[ixj];
                    bool up = ((i & k) == 0);
                    if ((a > c) == up) { sidx[i] = c; sidx[ixj] = a; }
                }
            }
            __syncthreads();
        }

    if (t < KK) {
        topidx[b * KK + t] = sidx[t];
        out[O_TOPIDX + b * KK + t] = (float)sidx[t];
    }
    if (t == 0) {
        int len = (int)ceilf((float)seqlen[b] * 0.4f);
        splen[b] = len;
        out[O_SPLEN + b] = (float)len;
    }
}

// ---------------------------------------------------------------------------
__global__ void gather_kernel(const float* __restrict__ span_vecs,
                              const int* __restrict__ span_begin,
                              const int* __restrict__ span_end,
                              const int* __restrict__ topidx,
                              float* __restrict__ out)
{
    int blk = blockIdx.x;
    int b = blk / KK, k = blk % KK;
    int idx = topidx[b * KK + k];
    const float4* src = reinterpret_cast<const float4*>(span_vecs + ((size_t)b * TL + idx) * DD);
    float4* dst = reinterpret_cast<float4*>(out + O_FVECS + ((size_t)b * KK + k) * DD);
#pragma unroll
    for (int p = 0; p < 2; p++)
        dst[threadIdx.x + p * 256] = src[threadIdx.x + p * 256];
    if (threadIdx.x == 0) {
        int g = b * TL + idx;
        out[O_FSCORE + b * KK + k] = out[O_PSCORE + g];
        out[O_FBEGIN + b * KK + k] = (float)span_begin[g];
        out[O_FEND   + b * KK + k] = (float)span_end[g];
    }
}

__global__ void mask_kernel(const int* __restrict__ splen, float* __restrict__ out)
{
    int i = blockIdx.x * blockDim.x + threadIdx.x;
    const int per = KK * KK;
    if (i >= BB * per) return;
    int b = i / per, r = i % per;
    int ii = r / KK, jj = r % KK;
    int len = splen[b];
    float v = (ii < len && jj < len) ? 1.0f : 0.0f;
    out[O_SQMASK + i] = v;
    out[O_TRMASK + i] = (jj <= ii) ? v : 0.0f;
}

// ---------------------------------------------------------------------------
extern "C" void kernel_launch(void* const* d_in, const int* in_sizes, int n_in,
                              void* d_out, int out_size)
{
    const float* span_vecs  = (const float*)d_in[0];
    const float* span_mask  = (const float*)d_in[1];
    const int*   span_begin = (const int*)  d_in[2];
    const int*   span_end   = (const int*)  d_in[3];
    const int*   seqlen     = (const int*)  d_in[4];
    const float* W1 = (const float*)d_in[5];
    const float* b1 = (const float*)d_in[6];
    const float* W2 = (const float*)d_in[7];
    const float* b2 = (const float*)d_in[8];
    const float* W3 = (const float*)d_in[9];
    const float* b3 = (const float*)d_in[10];
    float* out = (float*)d_out;

    __nv_bfloat16 *xhi, *xlo, *h1hi, *h1lo, *w1thi, *w1tlo, *w2thi, *w2tlo;
    float* spart; unsigned long long* cand; int *topidx, *splen;
    cudaGetSymbolAddress((void**)&xhi,   g_xhi);
    cudaGetSymbolAddress((void**)&xlo,   g_xlo);
    cudaGetSymbolAddress((void**)&h1hi,  g_h1hi);
    cudaGetSymbolAddress((void**)&h1lo,  g_h1lo);
    cudaGetSymbolAddress((void**)&w1thi, g_w1thi);
    cudaGetSymbolAddress((void**)&w1tlo, g_w1tlo);
    cudaGetSymbolAddress((void**)&w2thi, g_w2thi);
    cudaGetSymbolAddress((void**)&w2tlo, g_w2tlo);
    cudaGetSymbolAddress((void**)&spart, g_spart);
    cudaGetSymbolAddress((void**)&cand,  g_cand);
    cudaGetSymbolAddress((void**)&topidx, g_topidx);
    cudaGetSymbolAddress((void**)&splen,  g_spanlen);

    cudaFuncSetAttribute(gemm3_mma<1>, cudaFuncAttributeMaxDynamicSharedMemorySize, GEMM_SMEM);
    cudaFuncSetAttribute(gemm3_mma<2>, cudaFuncAttributeMaxDynamicSharedMemorySize, GEMM_SMEM);

    // 1) split inputs + weights into hi/lo bf16 (WT is [N][K], K-major)
    {
        size_t n8 = (size_t)MM * DD / 8;
        split_kernel<<<(unsigned)((n8 + 255) / 256), 256>>>((const float4*)span_vecs,
                                                            (uint4*)xhi, (uint4*)xlo, n8);
    }
    {
        size_t n = (size_t)DD * HH;
        transpose_split<<<(unsigned)((n + 255) / 256), 256>>>(W1, w1thi, w1tlo, DD, HH);
    }
    {
        size_t n = (size_t)HH * HH;
        transpose_split<<<(unsigned)((n + 255) / 256), 256>>>(W2, w2thi, w2tlo, HH, HH);
    }

    // 2) GEMM1: relu(x @ W1 + b1) -> h1 (split bf16 hi/lo)
    {
        dim3 grid(HH / GBN, MM / GBM);   // (8, 240)
        gemm3_mma<1><<<grid, 256, GEMM_SMEM>>>(xhi, xlo, w1thi, w1tlo, b1,
                                               nullptr, nullptr, h1hi, h1lo, MM, HH, DD);
    }
    // 3) GEMM2 + fused W3 GEMV -> score partials (h2 never materialized)
    {
        dim3 grid(HH / GBN, MM / GBM);
        gemm3_mma<2><<<grid, 256, GEMM_SMEM>>>(h1hi, h1lo, w2thi, w2tlo, b2,
                                               W3, spart, nullptr, nullptr, MM, HH, HH);
    }

    // 4) top-K: phase A fused with score finalization, then phase B
    topk_phaseA<<<BB * NSEG, 512>>>(spart, b3, span_mask, out, cand);
    topk_phaseB<<<BB, 1024>>>(cand, seqlen, out, topidx, splen);

    // 5) gathers
    gather_kernel<<<BB * KK, 256>>>(span_vecs, span_begin, span_end, topidx, out);

    // 6) masks
    {
        int n = BB * KK * KK;
        mask_kernel<<<(n + 255) / 256, 256>>>(splen, out);
    }
}

// round 10
// speedup vs baseline: 1.0906x; 1.0080x over previous
#include <cuda_runtime.h>
#include <cuda_bf16.h>
#include <cstdint>

// ---------------------------------------------------------------------------
// MentionPrunerSpanBert: B=4, T=512, L=15, D=2048, H=1024, K=205
// R9: smem-tiled transpose_split (fixes 32x read amplification: strided
//     column reads -> coalesced 32x32 tiles). GEMM/topk structure = R8.
// ---------------------------------------------------------------------------

#define BB   4
#define TT   512
#define LL   15
#define DD   2048
#define HH   1024
#define KK   205
#define TL   (TT * LL)          // 7680
#define MM   (BB * TL)          // 30720
#define NPART 8
#define NSEG 8
#define SEGLEN (TL / NSEG)      // 960

#define O_PSCORE 0
#define O_TOPIDX (O_PSCORE + MM)
#define O_FVECS  (O_TOPIDX + BB * KK)
#define O_FSCORE (O_FVECS  + (size_t)BB * KK * DD)
#define O_FBEGIN (O_FSCORE + BB * KK)
#define O_FEND   (O_FBEGIN + BB * KK)
#define O_SPLEN  (O_FEND   + BB * KK)
#define O_SQMASK (O_SPLEN  + BB)
#define O_TRMASK (O_SQMASK + BB * KK * KK)

// ---------------- device scratch (no allocations allowed) -------------------
__device__ __nv_bfloat16 g_xhi[(size_t)MM * DD];
__device__ __nv_bfloat16 g_xlo[(size_t)MM * DD];
__device__ __nv_bfloat16 g_h1hi[(size_t)MM * HH];
__device__ __nv_bfloat16 g_h1lo[(size_t)MM * HH];
__device__ __nv_bfloat16 g_w1thi[(size_t)HH * DD];
__device__ __nv_bfloat16 g_w1tlo[(size_t)HH * DD];
__device__ __nv_bfloat16 g_w2thi[(size_t)HH * HH];
__device__ __nv_bfloat16 g_w2tlo[(size_t)HH * HH];
__device__ float g_spart[(size_t)MM * NPART];
__device__ unsigned long long g_cand[BB * NSEG * KK];
__device__ int   g_topidx[BB * KK];
__device__ int   g_spanlen[BB];

// ---------------- PTX helpers (all arch-agnostic, sm_80+) -------------------
__device__ __forceinline__ uint32_t smem_u32_of(const void* p) {
    uint32_t a;
    asm("{ .reg .u64 t; cvta.to.shared.u64 t, %1; cvt.u32.u64 %0, t; }" : "=r"(a) : "l"(p));
    return a;
}
#define CP16(dst, src) \
    asm volatile("cp.async.cg.shared.global [%0], [%1], 16;" :: "r"((uint32_t)(dst)), "l"(src))
#define CP_COMMIT() asm volatile("cp.async.commit_group;" ::: "memory")
#define CP_WAIT(n)  asm volatile("cp.async.wait_group %0;" :: "n"(n) : "memory")

#define LDSM_X4(R0, R1, R2, R3, addr) \
    asm volatile("ldmatrix.sync.aligned.m8n8.x4.shared.b16 {%0,%1,%2,%3}, [%4];" \
        : "=r"(R0), "=r"(R1), "=r"(R2), "=r"(R3) : "r"(addr))

#define MMA_BF16(D, A, B0, B1) \
    asm volatile("mma.sync.aligned.m16n8k16.row.col.f32.bf16.bf16.f32 " \
        "{%0,%1,%2,%3}, {%4,%5,%6,%7}, {%8,%9}, {%0,%1,%2,%3};" \
        : "+f"((D)[0]), "+f"((D)[1]), "+f"((D)[2]), "+f"((D)[3]) \
        : "r"((A)[0]), "r"((A)[1]), "r"((A)[2]), "r"((A)[3]), "r"(B0), "r"(B1))

__device__ __forceinline__ uint32_t swz(int row, int chunk) {
    return (uint32_t)(row * 64 + (((chunk) ^ ((row >> 1) & 3)) & 3) * 16);
}

__device__ __forceinline__ unsigned long long score_key(float s, int idx) {
    unsigned u = __float_as_uint(s);
    u = (u & 0x80000000u) ? ~u : (u | 0x80000000u);
    return ((unsigned long long)(~u) << 32) | (unsigned)idx;
}

__device__ __forceinline__ uint32_t pack_split_hi(float x, float y, uint32_t& lo) {
    __nv_bfloat16 h0 = __float2bfloat16(x);
    __nv_bfloat16 h1 = __float2bfloat16(y);
    __nv_bfloat16 l0 = __float2bfloat16(x - __bfloat162float(h0));
    __nv_bfloat16 l1 = __float2bfloat16(y - __bfloat162float(h1));
    __nv_bfloat162 hh; hh.x = h0; hh.y = h1;
    __nv_bfloat162 ll; ll.x = l0; ll.y = l1;
    lo = *reinterpret_cast<uint32_t*>(&ll);
    return *reinterpret_cast<uint32_t*>(&hh);
}

// ---------------------------------------------------------------------------
// Split x: 8 elements per thread, 16B stores
// ---------------------------------------------------------------------------
__global__ void split_kernel(const float4* __restrict__ x,
                             uint4* __restrict__ hi,
                             uint4* __restrict__ lo, size_t n8)
{
    size_t i = (size_t)blockIdx.x * blockDim.x + threadIdx.x;
    if (i >= n8) return;
    float4 a = x[2 * i], b = x[2 * i + 1];
    uint4 h, l;
    h.x = pack_split_hi(a.x, a.y, l.x);
    h.y = pack_split_hi(a.z, a.w, l.y);
    h.z = pack_split_hi(b.x, b.y, l.z);
    h.w = pack_split_hi(b.z, b.w, l.w);
    hi[i] = h;
    lo[i] = l;
}

// ---------------------------------------------------------------------------
// Tiled transpose-split: W [Kd,N] row-major -> WT [N,Kd] hi/lo bf16.
// 32x32 smem tile, coalesced reads (consecutive n) and writes (consecutive k).
// Block (32,8); each thread covers 4 rows of the tile.
// ---------------------------------------------------------------------------
__global__ void transpose_split_tiled(const float* __restrict__ W,
                                      __nv_bfloat16* __restrict__ Thi,
                                      __nv_bfloat16* __restrict__ Tlo,
                                      int Kd, int N)
{
    __shared__ float tile[32][33];
    const int kt = blockIdx.x * 32;     // K-tile base
    const int nt = blockIdx.y * 32;     // N-tile base
    const int tx = threadIdx.x;         // 0..31
    const int ty = threadIdx.y;         // 0..7

    // read: W[kt+row][nt+tx], coalesced in tx
#pragma unroll
    for (int p = 0; p < 4; p++) {
        int row = ty + p * 8;
        tile[row][tx] = W[(size_t)(kt + row) * N + nt + tx];
    }
    __syncthreads();

    // write: T[nt+row][kt+tx] = tile[tx][row], coalesced in tx
#pragma unroll
    for (int p = 0; p < 4; p++) {
        int row = ty + p * 8;
        float v = tile[tx][row];
        __nv_bfloat16 h = __float2bfloat16(v);
        size_t o = (size_t)(nt + row) * Kd + kt + tx;
        Thi[o] = h;
        Tlo[o] = __float2bfloat16(v - __bfloat162float(h));
    }
}

// ---------------------------------------------------------------------------
// Split-bf16 HMMA GEMM (proven): tile 128x128, BK=32, 256 thr,
// 3-stage cp.async, swizzled smem, one sync/chunk, mid-chunk prefetch,
// 2 CTAs/SM.  MODE 1: Chi/Clo out.  MODE 2: fused W3 GEMV partials.
// ---------------------------------------------------------------------------
#define GBM 128
#define GBN 128
#define GBK 32
#define SM_AH 0
#define SM_AL 8192
#define SM_BH 16384
#define SM_BL 24576
#define STAGE_SZ 32768
#define NSTAGE 3
#define GEMM_SMEM (NSTAGE * STAGE_SZ)

template <int MODE>
__global__ __launch_bounds__(256, 2)
void gemm3_mma(const __nv_bfloat16* __restrict__ Ahi, const __nv_bfloat16* __restrict__ Alo,
               const __nv_bfloat16* __restrict__ Bhi, const __nv_bfloat16* __restrict__ Blo,
               const float* __restrict__ bias,
               const float* __restrict__ W3,
               float* __restrict__ spart,
               __nv_bfloat16* __restrict__ Chi, __nv_bfloat16* __restrict__ Clo,
               int M, int N, int Kd)
{
    extern __shared__ char smem[];
    const uint32_t sb = smem_u32_of(smem);
    const int t = threadIdx.x;
    const int lane = t & 31;
    const int wid = t >> 5;
    const int wm = wid & 3;
    const int wn = wid >> 2;
    const int mBase = blockIdx.y * GBM;
    const int nBase = blockIdx.x * GBN;
    const int NC = Kd / GBK;

    float acc[2][8][4];
#pragma unroll
    for (int mi = 0; mi < 2; mi++)
#pragma unroll
        for (int ni = 0; ni < 8; ni++)
#pragma unroll
            for (int j = 0; j < 4; j++) acc[mi][ni][j] = 0.0f;

    auto load_stage = [&](int cidx, int buf) {
        const size_t ko = (size_t)cidx * GBK;
        const uint32_t stg = sb + buf * STAGE_SZ;
#pragma unroll
        for (int p = 0; p < 2; p++) {
            const int idx = t + p * 256;
            const int row = idx >> 2;
            const int c16 = idx & 3;
            const uint32_t doff = swz(row, c16);
            const size_t aoff = (size_t)(mBase + row) * Kd + ko + c16 * 8;
            const size_t boff = (size_t)(nBase + row) * Kd + ko + c16 * 8;
            CP16(stg + SM_AH + doff, Ahi + aoff);
            CP16(stg + SM_AL + doff, Alo + aoff);
            CP16(stg + SM_BH + doff, Bhi + boff);
            CP16(stg + SM_BL + doff, Blo + boff);
        }
        CP_COMMIT();
    };

    const int ar = lane & 15, ac = lane >> 4;
    const int br = lane & 7,  bblk = lane >> 3;

    auto compute_half = [&](uint32_t stg, int kk2) {
        uint32_t ah[2][4], al[2][4];
#pragma unroll
        for (int mi = 0; mi < 2; mi++) {
            const int rowA = wm * 32 + mi * 16 + ar;
            const uint32_t ra = swz(rowA, kk2 * 2 + ac);
            LDSM_X4(ah[mi][0], ah[mi][1], ah[mi][2], ah[mi][3], stg + SM_AH + ra);
            LDSM_X4(al[mi][0], al[mi][1], al[mi][2], al[mi][3], stg + SM_AL + ra);
        }
        uint32_t bf[8][2];
#pragma unroll
        for (int nj = 0; nj < 4; nj++) {
            const int rowB = wn * 64 + nj * 16 + (bblk >> 1) * 8 + br;
            const uint32_t rb = swz(rowB, kk2 * 2 + (bblk & 1));
            LDSM_X4(bf[2*nj][0], bf[2*nj][1], bf[2*nj+1][0], bf[2*nj+1][1], stg + SM_BH + rb);
        }
#pragma unroll
        for (int mi = 0; mi < 2; mi++)
#pragma unroll
            for (int ni = 0; ni < 8; ni++) {
                MMA_BF16(acc[mi][ni], ah[mi], bf[ni][0], bf[ni][1]);
                MMA_BF16(acc[mi][ni], al[mi], bf[ni][0], bf[ni][1]);
            }
#pragma unroll
        for (int nj = 0; nj < 4; nj++) {
            const int rowB = wn * 64 + nj * 16 + (bblk >> 1) * 8 + br;
            const uint32_t rb = swz(rowB, kk2 * 2 + (bblk & 1));
            LDSM_X4(bf[2*nj][0], bf[2*nj][1], bf[2*nj+1][0], bf[2*nj+1][1], stg + SM_BL + rb);
        }
#pragma unroll
        for (int mi = 0; mi < 2; mi++)
#pragma unroll
            for (int ni = 0; ni < 8; ni++)
                MMA_BF16(acc[mi][ni], ah[mi], bf[ni][0], bf[ni][1]);
    };

    load_stage(0, 0);
    load_stage(1, 1);

#pragma unroll 1
    for (int c = 0; c < NC; c++) {
        const int buf = c % NSTAGE;
        if (c < NC - 1) CP_WAIT(1); else CP_WAIT(0);
        __syncthreads();
        const uint32_t stg = sb + buf * STAGE_SZ;
        compute_half(stg, 0);
        if (c + 2 < NC) load_stage(c + 2, (c + 2) % NSTAGE);
        compute_half(stg, 1);
    }

    // ---- epilogue ----
    const int r0 = lane >> 2;
    const int c0 = (lane & 3) << 1;

    if (MODE == 1) {
#pragma unroll
        for (int mi = 0; mi < 2; mi++) {
            const int rowA = mBase + wm * 32 + mi * 16 + r0;
#pragma unroll
            for (int ni = 0; ni < 8; ni++) {
                const int col = nBase + wn * 64 + ni * 8 + c0;
                const float bv0 = bias[col], bv1 = bias[col + 1];
                float v0 = acc[mi][ni][0] + bv0;  v0 = v0 > 0.0f ? v0 : 0.0f;
                float v1 = acc[mi][ni][1] + bv1;  v1 = v1 > 0.0f ? v1 : 0.0f;
                float v2 = acc[mi][ni][2] + bv0;  v2 = v2 > 0.0f ? v2 : 0.0f;
                float v3 = acc[mi][ni][3] + bv1;  v3 = v3 > 0.0f ? v3 : 0.0f;
                uint32_t hh, ll;
                hh = pack_split_hi(v0, v1, ll);
                *reinterpret_cast<uint32_t*>(Chi + (size_t)rowA * N + col) = hh;
                *reinterpret_cast<uint32_t*>(Clo + (size_t)rowA * N + col) = ll;
                hh = pack_split_hi(v2, v3, ll);
                *reinterpret_cast<uint32_t*>(Chi + (size_t)(rowA + 8) * N + col) = hh;
                *reinterpret_cast<uint32_t*>(Clo + (size_t)(rowA + 8) * N + col) = ll;
            }
        }
    } else {
        float ps[2][2] = {{0.0f, 0.0f}, {0.0f, 0.0f}};
#pragma unroll
        for (int mi = 0; mi < 2; mi++) {
#pragma unroll
            for (int ni = 0; ni < 8; ni++) {
                const int col = nBase + wn * 64 + ni * 8 + c0;
                const float bv0 = bias[col], bv1 = bias[col + 1];
                const float w0 = W3[col], w1 = W3[col + 1];
                float v0 = acc[mi][ni][0] + bv0;  v0 = v0 > 0.0f ? v0 : 0.0f;
                float v1 = acc[mi][ni][1] + bv1;  v1 = v1 > 0.0f ? v1 : 0.0f;
                float v2 = acc[mi][ni][2] + bv0;  v2 = v2 > 0.0f ? v2 : 0.0f;
                float v3 = acc[mi][ni][3] + bv1;  v3 = v3 > 0.0f ? v3 : 0.0f;
                ps[mi][0] = fmaf(v0, w0, fmaf(v1, w1, ps[mi][0]));
                ps[mi][1] = fmaf(v2, w0, fmaf(v3, w1, ps[mi][1]));
            }
#pragma unroll
            for (int o = 1; o <= 2; o <<= 1) {
                ps[mi][0] += __shfl_xor_sync(0xffffffffu, ps[mi][0], o);
                ps[mi][1] += __shfl_xor_sync(0xffffffffu, ps[mi][1], o);
            }
        }
        float* pssum = reinterpret_cast<float*>(smem);
        __syncthreads();
        if ((lane & 3) == 0) {
#pragma unroll
            for (int mi = 0; mi < 2; mi++) {
                int lr = wm * 32 + mi * 16 + r0;
                pssum[(lr)     * 2 + wn] = ps[mi][0];
                pssum[(lr + 8) * 2 + wn] = ps[mi][1];
            }
        }
        __syncthreads();
        if (t < 128) {
            float s = pssum[t * 2] + pssum[t * 2 + 1];
            spart[(size_t)(mBase + t) * NPART + blockIdx.x] = s;
        }
    }
}

// ---------------------------------------------------------------------------
// Top-K phase A (fused with score finish): 32 blocks (batch x 8 segments).
// ---------------------------------------------------------------------------
__global__ void topk_phaseA(const float* __restrict__ spart,
                            const float* __restrict__ b3,
                            const float* __restrict__ mask,
                            float* __restrict__ out,
                            unsigned long long* __restrict__ cand)
{
    __shared__ unsigned long long key[1024];
    const int b = blockIdx.x >> 3;
    const int seg = blockIdx.x & 7;
    const int t = threadIdx.x;          // 512
    const int base = seg * SEGLEN;
    const float bias3 = b3[0];

    for (int i = t; i < 1024; i += 512) {
        unsigned long long kv = 0xFFFFFFFFFFFFFFFFull;
        if (i < SEGLEN) {
            int gi = base + i;
            int row = b * TL + gi;
            const float* p = spart + (size_t)row * NPART;
            float s = bias3;
#pragma unroll
            for (int j = 0; j < NPART; j++) s += p[j];
            s -= (1.0f - mask[row]) * 10000.0f;
            out[O_PSCORE + row] = s;
            kv = score_key(s, gi);
        }
        key[i] = kv;
    }
    __syncthreads();

    for (int k = 2; k <= 1024; k <<= 1)
        for (int j = k >> 1; j > 0; j >>= 1) {
            for (int i = t; i < 1024; i += 512) {
                int ixj = i ^ j;
                if (ixj > i) {
                    unsigned long long a = key[i], c = key[ixj];
                    bool up = ((i & k) == 0);
                    if ((a > c) == up) { key[i] = c; key[ixj] = a; }
                }
            }
            __syncthreads();
        }

    if (t < KK) cand[(b * NSEG + seg) * KK + t] = key[t];
}

__global__ void topk_phaseB(const unsigned long long* __restrict__ cand,
                            const int* __restrict__ seqlen,
                            float* __restrict__ out,
                            int* __restrict__ topidx,
                            int* __restrict__ splen)
{
    __shared__ unsigned long long key[2048];
    const int b = blockIdx.x;
    const int t = threadIdx.x;          // 1024

    for (int i = t; i < 2048; i += 1024)
        key[i] = (i < NSEG * KK) ? cand[b * NSEG * KK + i] : 0xFFFFFFFFFFFFFFFFull;
    __syncthreads();

    for (int k = 2; k <= 2048; k <<= 1)
        for (int j = k >> 1; j > 0; j >>= 1) {
            for (int i = t; i < 2048; i += 1024) {
                int ixj = i ^ j;
                if (ixj > i) {
                    unsigned long long a = key[i], c = key[ixj];
                    bool up = ((i & k) == 0);
                    if ((a > c) == up) { key[i] = c; key[ixj] = a; }
                }
            }
            __syncthreads();
        }

    __shared__ int sidx[256];
    if (t < 256) sidx[t] = (t < KK) ? (int)(key[t] & 0xFFFFFFFFull) : 0x7FFFFFFF;
    __syncthreads();
    for (int k = 2; k <= 256; k <<= 1)
        for (int j = k >> 1; j > 0; j >>= 1) {
            if (t < 256) {
                int i = t, ixj = i ^ j;
                if (ixj > i) {
                    int a = sidx[i], c = sidx[ixj];
                    bool up = ((i & k) == 0);
                    if ((a > c) == up) { sidx[i] = c; sidx[ixj] = a; }
                }
            }
            __syncthreads();
        }

    if (t < KK) {
        topidx[b * KK + t] = sidx[t];
        out[O_TOPIDX + b * KK + t] = (float)sidx[t];
    }
    if (t == 0) {
        int len = (int)ceilf((float)seqlen[b] * 0.4f);
        splen[b] = len;
        out[O_SPLEN + b] = (float)len;
    }
}

// ---------------------------------------------------------------------------
__global__ void gather_kernel(const float* __restrict__ span_vecs,
                              const int* __restrict__ span_begin,
                              const int* __restrict__ span_end,
                              const int* __restrict__ topidx,
                              float* __restrict__ out)
{
    int blk = blockIdx.x;
    int b = blk / KK, k = blk % KK;
    int idx = topidx[b * KK + k];
    const float4* src = reinterpret_cast<const float4*>(span_vecs + ((size_t)b * TL + idx) * DD);
    float4* dst = reinterpret_cast<float4*>(out + O_FVECS + ((size_t)b * KK + k) * DD);
#pragma unroll
    for (int p = 0; p < 2; p++)
        dst[threadIdx.x + p * 256] = src[threadIdx.x + p * 256];
    if (threadIdx.x == 0) {
        int g = b * TL + idx;
        out[O_FSCORE + b * KK + k] = out[O_PSCORE + g];
        out[O_FBEGIN + b * KK + k] = (float)span_begin[g];
        out[O_FEND   + b * KK + k] = (float)span_end[g];
    }
}

__global__ void mask_kernel(const int* __restrict__ splen, float* __restrict__ out)
{
    int i = blockIdx.x * blockDim.x + threadIdx.x;
    const int per = KK * KK;
    if (i >= BB * per) return;
    int b = i / per, r = i % per;
    int ii = r / KK, jj = r % KK;
    int len = splen[b];
    float v = (ii < len && jj < len) ? 1.0f : 0.0f;
    out[O_SQMASK + i] = v;
    out[O_TRMASK + i] = (jj <= ii) ? v : 0.0f;
}

// ---------------------------------------------------------------------------
extern "C" void kernel_launch(void* const* d_in, const int* in_sizes, int n_in,
                              void* d_out, int out_size)
{
    const float* span_vecs  = (const float*)d_in[0];
    const float* span_mask  = (const float*)d_in[1];
    const int*   span_begin = (const int*)  d_in[2];
    const int*   span_end   = (const int*)  d_in[3];
    const int*   seqlen     = (const int*)  d_in[4];
    const float* W1 = (const float*)d_in[5];
    const float* b1 = (const float*)d_in[6];
    const float* W2 = (const float*)d_in[7];
    const float* b2 = (const float*)d_in[8];
    const float* W3 = (const float*)d_in[9];
    const float* b3 = (const float*)d_in[10];
    float* out = (float*)d_out;

    __nv_bfloat16 *xhi, *xlo, *h1hi, *h1lo, *w1thi, *w1tlo, *w2thi, *w2tlo;
    float* spart; unsigned long long* cand; int *topidx, *splen;
    cudaGetSymbolAddress((void**)&xhi,   g_xhi);
    cudaGetSymbolAddress((void**)&xlo,   g_xlo);
    cudaGetSymbolAddress((void**)&h1hi,  g_h1hi);
    cudaGetSymbolAddress((void**)&h1lo,  g_h1lo);
    cudaGetSymbolAddress((void**)&w1thi, g_w1thi);
    cudaGetSymbolAddress((void**)&w1tlo, g_w1tlo);
    cudaGetSymbolAddress((void**)&w2thi, g_w2thi);
    cudaGetSymbolAddress((void**)&w2tlo, g_w2tlo);
    cudaGetSymbolAddress((void**)&spart, g_spart);
    cudaGetSymbolAddress((void**)&cand,  g_cand);
    cudaGetSymbolAddress((void**)&topidx, g_topidx);
    cudaGetSymbolAddress((void**)&splen,  g_spanlen);

    cudaFuncSetAttribute(gemm3_mma<1>, cudaFuncAttributeMaxDynamicSharedMemorySize, GEMM_SMEM);
    cudaFuncSetAttribute(gemm3_mma<2>, cudaFuncAttributeMaxDynamicSharedMemorySize, GEMM_SMEM);

    // 1) split x + tiled transpose-split of weights
    {
        size_t n8 = (size_t)MM * DD / 8;
        split_kernel<<<(unsigned)((n8 + 255) / 256), 256>>>((const float4*)span_vecs,
                                                            (uint4*)xhi, (uint4*)xlo, n8);
    }
    {
        dim3 grid(DD / 32, HH / 32), blk(32, 8);
        transpose_split_tiled<<<grid, blk>>>(W1, w1thi, w1tlo, DD, HH);
    }
    {
        dim3 grid(HH / 32, HH / 32), blk(32, 8);
        transpose_split_tiled<<<grid, blk>>>(W2, w2thi, w2tlo, HH, HH);
    }

    // 2) GEMM1: relu(x @ W1 + b1) -> h1 (split bf16 hi/lo)
    {
        dim3 grid(HH / GBN, MM / GBM);   // (8, 240)
        gemm3_mma<1><<<grid, 256, GEMM_SMEM>>>(xhi, xlo, w1thi, w1tlo, b1,
                                               nullptr, nullptr, h1hi, h1lo, MM, HH, DD);
    }
    // 3) GEMM2 + fused W3 GEMV -> score partials (h2 never materialized)
    {
        dim3 grid(HH / GBN, MM / GBM);
        gemm3_mma<2><<<grid, 256, GEMM_SMEM>>>(h1hi, h1lo, w2thi, w2tlo, b2,
                                               W3, spart, nullptr, nullptr, MM, HH, HH);
    }

    // 4) top-K: phase A fused with score finalization, then phase B
    topk_phaseA<<<BB * NSEG, 512>>>(spart, b3, span_mask, out, cand);
    topk_phaseB<<<BB, 1024>>>(cand, seqlen, out, topidx, splen);

    // 5) gathers
    gather_kernel<<<BB * KK, 256>>>(span_vecs, span_begin, span_end, topidx, out);

    // 6) masks
    {
        int n = BB * KK * KK;
        mask_kernel<<<(n + 255) / 256, 256>>>(splen, out);
    }
}